// round 1
// baseline (speedup 1.0000x reference)
#include <cuda_runtime.h>
#include <math.h>

// Problem constants (shapes fixed by the reference)
#define NPTS   262144
#define BATCH  4
#define HG     200
#define WGRID  176
#define HW     35200      // 200*176
#define CBEV   256
#define CDIR   176        // 16+32+64+64
#define CIN    432
#define COUT   128
#define NPIX   (BATCH * HW)   // 140800

// Scratch: projected BEV features G[pixel][128] = im[pixel][0:256] @ W[:,176:432]^T
__device__ float g_G[(size_t)NPIX * COUT];   // 72.1 MB

// ---------------------------------------------------------------------------
// Kernel A: project spatial_features (B,256,H,W) -> G (B*H*W, 128)
// GEMM: M=140800 (pixels), N=128, K=256.  A[p,c] has stride HW in c, contiguous in p.
// ---------------------------------------------------------------------------
__global__ __launch_bounds__(256, 2)
void proj_kernel(const float* __restrict__ sp, const float* __restrict__ Wmat) {
    __shared__ float As[16][128];   // [k][m]
    __shared__ float Bs[16][128];   // [k][n]

    const int t = threadIdx.x;
    const int pixBase = blockIdx.x * 128;          // 35200 % 128 == 0: tile never crosses batch
    const int b = pixBase / HW;
    const int pixInB = pixBase - b * HW;
    const float* Abase = sp + (size_t)b * CBEV * HW + pixInB;
    const int tm = t >> 4, tn = t & 15;

    float acc[8][8];
    #pragma unroll
    for (int i = 0; i < 8; i++)
        #pragma unroll
        for (int j = 0; j < 8; j++) acc[i][j] = 0.0f;

    for (int k0 = 0; k0 < CBEV; k0 += 16) {
        // Load A tile: 16 channel-rows x 128 contiguous pixels (fully coalesced)
        #pragma unroll
        for (int i = 0; i < 2; i++) {
            int lin = t + i * 256;
            int k   = lin >> 5;
            int m4  = (lin & 31) << 2;
            *(float4*)&As[k][m4] =
                *(const float4*)(Abase + (size_t)(k0 + k) * HW + m4);
        }
        // Load B tile: W[n, 176+k0+k], transpose to [k][n]
        #pragma unroll
        for (int i = 0; i < 2; i++) {
            int lin = t + i * 256;
            int n   = lin & 127;
            int k4  = (lin >> 7) << 2;
            float4 v = *(const float4*)(Wmat + (size_t)n * CIN + CDIR + k0 + k4);
            Bs[k4 + 0][n] = v.x; Bs[k4 + 1][n] = v.y;
            Bs[k4 + 2][n] = v.z; Bs[k4 + 3][n] = v.w;
        }
        __syncthreads();
        #pragma unroll
        for (int kk = 0; kk < 16; kk++) {
            float a[8], bb[8];
            *(float4*)&a[0]  = *(const float4*)&As[kk][tm * 8];
            *(float4*)&a[4]  = *(const float4*)&As[kk][tm * 8 + 4];
            *(float4*)&bb[0] = *(const float4*)&Bs[kk][tn * 8];
            *(float4*)&bb[4] = *(const float4*)&Bs[kk][tn * 8 + 4];
            #pragma unroll
            for (int i = 0; i < 8; i++)
                #pragma unroll
                for (int j = 0; j < 8; j++)
                    acc[i][j] += a[i] * bb[j];
        }
        __syncthreads();
    }

    float* gout = g_G + (size_t)pixBase * COUT;
    #pragma unroll
    for (int i = 0; i < 8; i++) {
        int m = tm * 8 + i;
        *(float4*)&gout[(size_t)m * COUT + tn * 8] =
            make_float4(acc[i][0], acc[i][1], acc[i][2], acc[i][3]);
        *(float4*)&gout[(size_t)m * COUT + tn * 8 + 4] =
            make_float4(acc[i][4], acc[i][5], acc[i][6], acc[i][7]);
    }
}

// ---------------------------------------------------------------------------
// Kernel B: per-point direct-feature GEMM (K=176) + bilinear gather of G
//           (4 x 512B contiguous rows, weighted) + BN + ReLU.
// Tile: 128 points x 128 outputs per block, 256 threads, 8x8 per thread.
// ---------------------------------------------------------------------------
#define ASTR 132   // padded stride for transposed A stores

__global__ __launch_bounds__(256, 2)
void point_kernel(const float* __restrict__ pc,
                  const float* __restrict__ f16,
                  const float* __restrict__ f32,
                  const float* __restrict__ f64a,
                  const float* __restrict__ f64b,
                  const float* __restrict__ Wmat,
                  const float* __restrict__ gamma,
                  const float* __restrict__ beta,
                  const float* __restrict__ mean,
                  const float* __restrict__ var,
                  float* __restrict__ out) {
    __shared__ float As[16][ASTR];
    __shared__ float Bs[16][128];
    __shared__ int   pixs[4][128];
    __shared__ float wgts[4][128];
    __shared__ float scale_s[128];
    __shared__ float shift_s[128];

    const int t = threadIdx.x;
    const int mBase = blockIdx.x * 128;
    const int tm = t >> 4, tn = t & 15;

    if (t < 128) {
        // Bilinear parameters, exactly mirroring the reference math
        float4 p = *(const float4*)(pc + (size_t)(mBase + t) * 4);
        int   b = (int)p.x;
        float x = (p.y - 0.0f) / 0.05f / 8.0f;
        float y = (p.z - (-40.0f)) / 0.05f / 8.0f;
        int xf = (int)floorf(x);
        int yf = (int)floorf(y);
        int x0 = min(max(xf,     0), WGRID - 1);
        int x1 = min(max(xf + 1, 0), WGRID - 1);
        int y0 = min(max(yf,     0), HG - 1);
        int y1 = min(max(yf + 1, 0), HG - 1);
        float xf0 = (float)x0, xf1 = (float)x1;
        float yf0 = (float)y0, yf1 = (float)y1;
        int base = b * HW;
        pixs[0][t] = base + y0 * WGRID + x0;
        pixs[1][t] = base + y1 * WGRID + x0;
        pixs[2][t] = base + y0 * WGRID + x1;
        pixs[3][t] = base + y1 * WGRID + x1;
        wgts[0][t] = (xf1 - x) * (yf1 - y);
        wgts[1][t] = (xf1 - x) * (y - yf0);
        wgts[2][t] = (x - xf0) * (yf1 - y);
        wgts[3][t] = (x - xf0) * (y - yf0);
    } else {
        int n = t - 128;
        float s = gamma[n] * rsqrtf(var[n] + 1e-5f);
        scale_s[n] = s;
        shift_s[n] = beta[n] - mean[n] * s;
    }
    // (first __syncthreads inside the k-loop orders the above before any use)

    float acc[8][8];
    #pragma unroll
    for (int i = 0; i < 8; i++)
        #pragma unroll
        for (int j = 0; j < 8; j++) acc[i][j] = 0.0f;

    // Direct-feature GEMM, K=176 in 11 tiles of 16; each tile lies in one segment.
    for (int k0 = 0; k0 < CDIR; k0 += 16) {
        const float* fb; int s, off;
        if (k0 < 16)       { fb = f16;  s = 16; off = k0;       }
        else if (k0 < 48)  { fb = f32;  s = 32; off = k0 - 16;  }
        else if (k0 < 112) { fb = f64a; s = 64; off = k0 - 48;  }
        else               { fb = f64b; s = 64; off = k0 - 112; }

        #pragma unroll
        for (int i = 0; i < 2; i++) {
            int lin = t + i * 256;
            int m   = lin >> 2;
            int k4  = (lin & 3) << 2;
            float4 v = *(const float4*)(fb + (size_t)(mBase + m) * s + off + k4);
            As[k4 + 0][m] = v.x; As[k4 + 1][m] = v.y;
            As[k4 + 2][m] = v.z; As[k4 + 3][m] = v.w;
        }
        #pragma unroll
        for (int i = 0; i < 2; i++) {
            int lin = t + i * 256;
            int n   = lin & 127;
            int k4  = (lin >> 7) << 2;
            float4 v = *(const float4*)(Wmat + (size_t)n * CIN + k0 + k4);
            Bs[k4 + 0][n] = v.x; Bs[k4 + 1][n] = v.y;
            Bs[k4 + 2][n] = v.z; Bs[k4 + 3][n] = v.w;
        }
        __syncthreads();
        #pragma unroll
        for (int kk = 0; kk < 16; kk++) {
            float a[8], bb[8];
            *(float4*)&a[0]  = *(const float4*)&As[kk][tm * 8];
            *(float4*)&a[4]  = *(const float4*)&As[kk][tm * 8 + 4];
            *(float4*)&bb[0] = *(const float4*)&Bs[kk][tn * 8];
            *(float4*)&bb[4] = *(const float4*)&Bs[kk][tn * 8 + 4];
            #pragma unroll
            for (int i = 0; i < 8; i++)
                #pragma unroll
                for (int j = 0; j < 8; j++)
                    acc[i][j] += a[i] * bb[j];
        }
        __syncthreads();
    }

    // BEV contribution: 4 weighted contiguous 128-float rows of G per point.
    // Each thread touches its own 8 n-columns (2 float4s) of each row. G is L2-hot.
    #pragma unroll
    for (int r = 0; r < 8; r++) {
        int m = tm * 8 + r;
        #pragma unroll
        for (int i = 0; i < 4; i++) {
            float w = wgts[i][m];
            const float* gp = g_G + (size_t)pixs[i][m] * COUT + tn * 8;
            float4 v0 = *(const float4*)gp;
            float4 v1 = *(const float4*)(gp + 4);
            acc[r][0] += w * v0.x; acc[r][1] += w * v0.y;
            acc[r][2] += w * v0.z; acc[r][3] += w * v0.w;
            acc[r][4] += w * v1.x; acc[r][5] += w * v1.y;
            acc[r][6] += w * v1.z; acc[r][7] += w * v1.w;
        }
    }

    // BN + ReLU epilogue, vectorized store
    #pragma unroll
    for (int r = 0; r < 8; r++) {
        int m = mBase + tm * 8 + r;
        float o[8];
        #pragma unroll
        for (int j = 0; j < 8; j++) {
            int n = tn * 8 + j;
            o[j] = fmaxf(acc[r][j] * scale_s[n] + shift_s[n], 0.0f);
        }
        *(float4*)&out[(size_t)m * COUT + tn * 8]     = make_float4(o[0], o[1], o[2], o[3]);
        *(float4*)&out[(size_t)m * COUT + tn * 8 + 4] = make_float4(o[4], o[5], o[6], o[7]);
    }
}

// ---------------------------------------------------------------------------
extern "C" void kernel_launch(void* const* d_in, const int* in_sizes, int n_in,
                              void* d_out, int out_size) {
    const float* point_coords = (const float*)d_in[0];
    const float* spatial      = (const float*)d_in[1];
    const float* feat16       = (const float*)d_in[2];
    const float* feat32       = (const float*)d_in[3];
    const float* feat64a      = (const float*)d_in[4];
    const float* feat64b      = (const float*)d_in[5];
    const float* Wmat         = (const float*)d_in[6];
    const float* gamma        = (const float*)d_in[7];
    const float* beta         = (const float*)d_in[8];
    const float* rmean        = (const float*)d_in[9];
    const float* rvar         = (const float*)d_in[10];
    float* out = (float*)d_out;

    proj_kernel<<<NPIX / 128, 256>>>(spatial, Wmat);
    point_kernel<<<NPTS / 128, 256>>>(point_coords, feat16, feat32, feat64a, feat64b,
                                      Wmat, gamma, beta, rmean, rvar, out);
}

// round 2
// speedup vs baseline: 2.3495x; 2.3495x over previous
#include <cuda_runtime.h>
#include <math.h>

#define NPTS   262144
#define BATCH  4
#define HG     200
#define WGRID  176
#define HW     35200
#define CBEV   256
#define CDIR   176
#define CIN    432
#define COUT   128
#define NPIX   (BATCH * HW)   // 140800

// Projected BEV features G[pixel][128] = im[pixel][:] @ W[:,176:432]^T
__device__ float g_G[(size_t)NPIX * COUT];   // 72.1 MB (fits L2)

// ---------------------------------------------------------------------------
// helpers
// ---------------------------------------------------------------------------
__device__ __forceinline__ unsigned smem_u32(const void* p) {
    unsigned a;
    asm("{ .reg .u64 t; cvta.to.shared.u64 t, %1; cvt.u32.u64 %0, t; }"
        : "=r"(a) : "l"(p));
    return a;
}
#define CP_ASYNC16(dst, src) \
    asm volatile("cp.async.cg.shared.global [%0], [%1], 16;\n" :: "r"(dst), "l"(src))
#define CP_COMMIT() asm volatile("cp.async.commit_group;\n")
#define CP_WAIT(n)  asm volatile("cp.async.wait_group %0;\n" :: "n"(n))

__device__ __forceinline__ unsigned f2tf(float x) {
    unsigned r;
    asm("cvt.rna.tf32.f32 %0, %1;" : "=r"(r) : "f"(x));
    return r;
}

__device__ __forceinline__ void mma_tf32(float* c, const unsigned* a, const unsigned* b) {
    asm volatile(
        "mma.sync.aligned.m16n8k8.row.col.f32.tf32.tf32.f32 "
        "{%0,%1,%2,%3},{%4,%5,%6,%7},{%8,%9},{%0,%1,%2,%3};"
        : "+f"(c[0]), "+f"(c[1]), "+f"(c[2]), "+f"(c[3])
        : "r"(a[0]), "r"(a[1]), "r"(a[2]), "r"(a[3]), "r"(b[0]), "r"(b[1]));
}

// ---------------------------------------------------------------------------
// Kernel A: G = im @ W_bev^T.  M=140800 (pixels), N=128, K=256.
// A global layout: [channel][pixel] (stride HW), contiguous in pixel.
// Tile 128x128, BK=16, 8 warps (4m x 2n), warp tile 32x64, tf32 mma.
// ---------------------------------------------------------------------------
#define ASTR_P 136   // proj As [k][m] stride (bank: (8k+m)%32 distinct)
#define BSTR   20    // Bs [n][k] stride    (bank: (20n+k)%32 distinct)

__global__ __launch_bounds__(256, 2)
void proj_kernel(const float* __restrict__ sp, const float* __restrict__ Wmat) {
    __shared__ float As[2][16][ASTR_P];
    __shared__ float Bs[2][128][BSTR];

    const int t    = threadIdx.x;
    const int lane = t & 31;
    const int wid  = t >> 5;
    const int wm   = wid & 3;     // 4 warps along m (32 rows each)
    const int wn   = wid >> 2;    // 2 warps along n (64 cols each)
    const int qg   = lane >> 2;   // group id
    const int ql   = lane & 3;    // thread in group

    const int pixBase = blockIdx.x * 128;      // 35200 % 128 == 0
    const int b       = pixBase / HW;
    const int pixInB  = pixBase - b * HW;
    const float* Abase = sp + (size_t)b * CBEV * HW + pixInB;

    const unsigned uA = smem_u32(&As[0][0][0]);
    const unsigned uB = smem_u32(&Bs[0][0][0]);

    float acc[2][8][4];
    #pragma unroll
    for (int i = 0; i < 2; i++)
        #pragma unroll
        for (int j = 0; j < 8; j++)
            #pragma unroll
            for (int v = 0; v < 4; v++) acc[i][j][v] = 0.0f;

    // stage loader: k0 = s*16
    auto load_stage = [&](int s, int buf) {
        int k0 = s * 16;
        // As: 16 k-rows x 128 pixels; 512 float4, 2 per thread
        #pragma unroll
        for (int i = 0; i < 2; i++) {
            int lin = t + i * 256;
            int k   = lin >> 5;
            int m4  = (lin & 31) << 2;
            unsigned dst = uA + ((unsigned)(buf * 16 + k) * ASTR_P + m4) * 4u;
            CP_ASYNC16(dst, Abase + (size_t)(k0 + k) * HW + m4);
        }
        // Bs: 128 n-rows x 16 k; src W[n][CDIR+k0 ...]
        #pragma unroll
        for (int i = 0; i < 2; i++) {
            int lin = t + i * 256;
            int n   = lin >> 2;
            int k4  = (lin & 3) << 2;
            unsigned dst = uB + ((unsigned)(buf * 128 + n) * BSTR + k4) * 4u;
            CP_ASYNC16(dst, Wmat + (size_t)n * CIN + CDIR + k0 + k4);
        }
        CP_COMMIT();
    };

    load_stage(0, 0);

    for (int s = 0; s < 16; s++) {
        int buf = s & 1;
        if (s + 1 < 16) { load_stage(s + 1, buf ^ 1); CP_WAIT(1); }
        else            { CP_WAIT(0); }
        __syncthreads();

        #pragma unroll
        for (int kk = 0; kk < 16; kk += 8) {
            int kc = kk + ql;
            unsigned a[2][4], bb[8][2];
            #pragma unroll
            for (int mt = 0; mt < 2; mt++) {
                int r = wm * 32 + mt * 16 + qg;
                a[mt][0] = f2tf(As[buf][kc][r]);
                a[mt][1] = f2tf(As[buf][kc][r + 8]);
                a[mt][2] = f2tf(As[buf][kc + 4][r]);
                a[mt][3] = f2tf(As[buf][kc + 4][r + 8]);
            }
            #pragma unroll
            for (int nt = 0; nt < 8; nt++) {
                int c = wn * 64 + nt * 8 + qg;
                bb[nt][0] = f2tf(Bs[buf][c][kc]);
                bb[nt][1] = f2tf(Bs[buf][c][kc + 4]);
            }
            #pragma unroll
            for (int mt = 0; mt < 2; mt++)
                #pragma unroll
                for (int nt = 0; nt < 8; nt++)
                    mma_tf32(acc[mt][nt], a[mt], bb[nt]);
        }
        __syncthreads();
    }

    // epilogue: write G
    #pragma unroll
    for (int mt = 0; mt < 2; mt++) {
        int r0 = pixBase + wm * 32 + mt * 16 + qg;
        #pragma unroll
        for (int nt = 0; nt < 8; nt++) {
            int n = wn * 64 + nt * 8 + 2 * ql;
            *(float2*)&g_G[(size_t)r0 * COUT + n] =
                make_float2(acc[mt][nt][0], acc[mt][nt][1]);
            *(float2*)&g_G[(size_t)(r0 + 8) * COUT + n] =
                make_float2(acc[mt][nt][2], acc[mt][nt][3]);
        }
    }
}

// ---------------------------------------------------------------------------
// Kernel B: direct-feature GEMM (K=176, tf32 mma) + bilinear gather of G
//           + BN + ReLU.  Tile 128 pts x 128 out, BK=16, warp tile 32x64.
// ---------------------------------------------------------------------------
#define ASTR_Q 20    // point As [m][k] stride (bank: (20m+k)%32 distinct)

__global__ __launch_bounds__(256, 2)
void point_kernel(const float* __restrict__ pc,
                  const float* __restrict__ f16,
                  const float* __restrict__ f32,
                  const float* __restrict__ f64a,
                  const float* __restrict__ f64b,
                  const float* __restrict__ Wmat,
                  const float* __restrict__ gamma,
                  const float* __restrict__ beta,
                  const float* __restrict__ mean,
                  const float* __restrict__ var,
                  float* __restrict__ out) {
    __shared__ float As[2][128][ASTR_Q];
    __shared__ float Bs[2][128][BSTR];
    __shared__ int   pixs[4][128];
    __shared__ float wgts[4][128];
    __shared__ float scale_s[128];
    __shared__ float shift_s[128];

    const int t    = threadIdx.x;
    const int lane = t & 31;
    const int wid  = t >> 5;
    const int wm   = wid & 3;
    const int wn   = wid >> 2;
    const int qg   = lane >> 2;
    const int ql   = lane & 3;

    const int mBase = blockIdx.x * 128;

    if (t < 128) {
        float4 p = *(const float4*)(pc + (size_t)(mBase + t) * 4);
        int   bb = (int)p.x;
        float x  = (p.y - 0.0f) / 0.05f / 8.0f;
        float y  = (p.z - (-40.0f)) / 0.05f / 8.0f;
        int xf = (int)floorf(x);
        int yf = (int)floorf(y);
        int x0 = min(max(xf,     0), WGRID - 1);
        int x1 = min(max(xf + 1, 0), WGRID - 1);
        int y0 = min(max(yf,     0), HG - 1);
        int y1 = min(max(yf + 1, 0), HG - 1);
        float xf0 = (float)x0, xf1 = (float)x1;
        float yf0 = (float)y0, yf1 = (float)y1;
        int base = bb * HW;
        pixs[0][t] = base + y0 * WGRID + x0;
        pixs[1][t] = base + y1 * WGRID + x0;
        pixs[2][t] = base + y0 * WGRID + x1;
        pixs[3][t] = base + y1 * WGRID + x1;
        wgts[0][t] = (xf1 - x) * (yf1 - y);
        wgts[1][t] = (xf1 - x) * (y - yf0);
        wgts[2][t] = (x - xf0) * (yf1 - y);
        wgts[3][t] = (x - xf0) * (y - yf0);
    } else {
        int n = t - 128;
        float s = gamma[n] * rsqrtf(var[n] + 1e-5f);
        scale_s[n] = s;
        shift_s[n] = beta[n] - mean[n] * s;
    }

    const unsigned uA = smem_u32(&As[0][0][0]);
    const unsigned uB = smem_u32(&Bs[0][0][0]);

    float acc[2][8][4];
    #pragma unroll
    for (int i = 0; i < 2; i++)
        #pragma unroll
        for (int j = 0; j < 8; j++)
            #pragma unroll
            for (int v = 0; v < 4; v++) acc[i][j][v] = 0.0f;

    auto load_stage = [&](int s, int buf) {
        int k0 = s * 16;
        const float* fb; int fs, off;
        if (k0 < 16)       { fb = f16;  fs = 16; off = k0;       }
        else if (k0 < 48)  { fb = f32;  fs = 32; off = k0 - 16;  }
        else if (k0 < 112) { fb = f64a; fs = 64; off = k0 - 48;  }
        else               { fb = f64b; fs = 64; off = k0 - 112; }
        // As: 128 rows x 16 k
        #pragma unroll
        for (int i = 0; i < 2; i++) {
            int lin = t + i * 256;
            int m   = lin >> 2;
            int k4  = (lin & 3) << 2;
            unsigned dst = uA + ((unsigned)(buf * 128 + m) * ASTR_Q + k4) * 4u;
            CP_ASYNC16(dst, fb + (size_t)(mBase + m) * fs + off + k4);
        }
        // Bs: 128 rows x 16 k
        #pragma unroll
        for (int i = 0; i < 2; i++) {
            int lin = t + i * 256;
            int n   = lin >> 2;
            int k4  = (lin & 3) << 2;
            unsigned dst = uB + ((unsigned)(buf * 128 + n) * BSTR + k4) * 4u;
            CP_ASYNC16(dst, Wmat + (size_t)n * CIN + k0 + k4);
        }
        CP_COMMIT();
    };

    load_stage(0, 0);

    for (int s = 0; s < 11; s++) {
        int buf = s & 1;
        if (s + 1 < 11) { load_stage(s + 1, buf ^ 1); CP_WAIT(1); }
        else            { CP_WAIT(0); }
        __syncthreads();

        #pragma unroll
        for (int kk = 0; kk < 16; kk += 8) {
            int kc = kk + ql;
            unsigned a[2][4], bb[8][2];
            #pragma unroll
            for (int mt = 0; mt < 2; mt++) {
                int r = wm * 32 + mt * 16 + qg;
                a[mt][0] = f2tf(As[buf][r][kc]);
                a[mt][1] = f2tf(As[buf][r + 8][kc]);
                a[mt][2] = f2tf(As[buf][r][kc + 4]);
                a[mt][3] = f2tf(As[buf][r + 8][kc + 4]);
            }
            #pragma unroll
            for (int nt = 0; nt < 8; nt++) {
                int c = wn * 64 + nt * 8 + qg;
                bb[nt][0] = f2tf(Bs[buf][c][kc]);
                bb[nt][1] = f2tf(Bs[buf][c][kc + 4]);
            }
            #pragma unroll
            for (int mt = 0; mt < 2; mt++)
                #pragma unroll
                for (int nt = 0; nt < 8; nt++)
                    mma_tf32(acc[mt][nt], a[mt], bb[nt]);
        }
        __syncthreads();
    }

    // BEV gather: acc[mt][nt][2h+{0,1}] += w * G[pix][n..n+1]
    #pragma unroll
    for (int mt = 0; mt < 2; mt++) {
        #pragma unroll
        for (int h = 0; h < 2; h++) {
            int ml = wm * 32 + mt * 16 + qg + h * 8;   // quad-uniform -> LDS broadcast
            #pragma unroll
            for (int nb = 0; nb < 4; nb++) {
                float w = wgts[nb][ml];
                const float* gp = g_G + (size_t)pixs[nb][ml] * COUT + wn * 64 + 2 * ql;
                #pragma unroll
                for (int nt = 0; nt < 8; nt++) {
                    float2 g = *(const float2*)(gp + nt * 8);
                    acc[mt][nt][2 * h + 0] += w * g.x;
                    acc[mt][nt][2 * h + 1] += w * g.y;
                }
            }
        }
    }

    // BN + ReLU + store
    #pragma unroll
    for (int nt = 0; nt < 8; nt++) {
        int n = wn * 64 + nt * 8 + 2 * ql;
        float s0 = scale_s[n],     h0 = shift_s[n];
        float s1 = scale_s[n + 1], h1 = shift_s[n + 1];
        #pragma unroll
        for (int mt = 0; mt < 2; mt++) {
            int m = mBase + wm * 32 + mt * 16 + qg;
            *(float2*)&out[(size_t)m * COUT + n] =
                make_float2(fmaxf(acc[mt][nt][0] * s0 + h0, 0.0f),
                            fmaxf(acc[mt][nt][1] * s1 + h1, 0.0f));
            *(float2*)&out[(size_t)(m + 8) * COUT + n] =
                make_float2(fmaxf(acc[mt][nt][2] * s0 + h0, 0.0f),
                            fmaxf(acc[mt][nt][3] * s1 + h1, 0.0f));
        }
    }
}

// ---------------------------------------------------------------------------
extern "C" void kernel_launch(void* const* d_in, const int* in_sizes, int n_in,
                              void* d_out, int out_size) {
    const float* point_coords = (const float*)d_in[0];
    const float* spatial      = (const float*)d_in[1];
    const float* feat16       = (const float*)d_in[2];
    const float* feat32       = (const float*)d_in[3];
    const float* feat64a      = (const float*)d_in[4];
    const float* feat64b      = (const float*)d_in[5];
    const float* Wmat         = (const float*)d_in[6];
    const float* gamma        = (const float*)d_in[7];
    const float* beta         = (const float*)d_in[8];
    const float* rmean        = (const float*)d_in[9];
    const float* rvar         = (const float*)d_in[10];
    float* out = (float*)d_out;

    proj_kernel<<<NPIX / 128, 256>>>(spatial, Wmat);
    point_kernel<<<NPTS / 128, 256>>>(point_coords, feat16, feat32, feat64a, feat64b,
                                      Wmat, gamma, beta, rmean, rvar, out);
}

// round 3
// speedup vs baseline: 2.4761x; 1.0539x over previous
#include <cuda_runtime.h>
#include <cuda_fp16.h>
#include <math.h>

#define NPTS   262144
#define BATCH  4
#define HG     200
#define WGRID  176
#define HW     35200
#define CBEV   256
#define CDIR   176
#define CIN    432
#define COUT   128
#define NPIX   (BATCH * HW)   // 140800

// Projected BEV features, fp16: G[pixel][128] = im[pixel][:] @ W[:,176:432]^T
__device__ __half g_G[(size_t)NPIX * COUT];   // 36 MB (L2-resident)

// ---------------------------------------------------------------------------
__device__ __forceinline__ unsigned smem_u32(const void* p) {
    unsigned a;
    asm("{ .reg .u64 t; cvta.to.shared.u64 t, %1; cvt.u32.u64 %0, t; }"
        : "=r"(a) : "l"(p));
    return a;
}
#define CP_ASYNC16(dst, src) \
    asm volatile("cp.async.cg.shared.global [%0], [%1], 16;\n" :: "r"(dst), "l"(src))
#define CP_COMMIT() asm volatile("cp.async.commit_group;\n")
#define CP_WAIT(n)  asm volatile("cp.async.wait_group %0;\n" :: "n"(n))

// Raw fp32 bits into tf32 MMA: HW uses the top 19 bits (RZ truncation).
__device__ __forceinline__ void mma_tf32(float* c, const unsigned* a, const unsigned* b) {
    asm volatile(
        "mma.sync.aligned.m16n8k8.row.col.f32.tf32.tf32.f32 "
        "{%0,%1,%2,%3},{%4,%5,%6,%7},{%8,%9},{%0,%1,%2,%3};"
        : "+f"(c[0]), "+f"(c[1]), "+f"(c[2]), "+f"(c[3])
        : "r"(a[0]), "r"(a[1]), "r"(a[2]), "r"(a[3]), "r"(b[0]), "r"(b[1]));
}

// ---------------------------------------------------------------------------
// Kernel A: G = im @ W_bev^T  (M=140800, N=128, K=256), output fp16.
// ---------------------------------------------------------------------------
#define ASTR_P 136
#define BSTR   20

__global__ __launch_bounds__(256, 2)
void proj_kernel(const float* __restrict__ sp, const float* __restrict__ Wmat) {
    __shared__ float As[2][16][ASTR_P];
    __shared__ float Bs[2][128][BSTR];

    const int t    = threadIdx.x;
    const int lane = t & 31;
    const int wid  = t >> 5;
    const int wm   = wid & 3;
    const int wn   = wid >> 2;
    const int qg   = lane >> 2;
    const int ql   = lane & 3;

    const int pixBase = blockIdx.x * 128;
    const int b       = pixBase / HW;
    const int pixInB  = pixBase - b * HW;
    const float* Abase = sp + (size_t)b * CBEV * HW + pixInB;

    const unsigned uA = smem_u32(&As[0][0][0]);
    const unsigned uB = smem_u32(&Bs[0][0][0]);

    float acc[2][8][4];
    #pragma unroll
    for (int i = 0; i < 2; i++)
        #pragma unroll
        for (int j = 0; j < 8; j++)
            #pragma unroll
            for (int v = 0; v < 4; v++) acc[i][j][v] = 0.0f;

    auto load_stage = [&](int s, int buf) {
        int k0 = s * 16;
        #pragma unroll
        for (int i = 0; i < 2; i++) {
            int lin = t + i * 256;
            int k   = lin >> 5;
            int m4  = (lin & 31) << 2;
            unsigned dst = uA + ((unsigned)(buf * 16 + k) * ASTR_P + m4) * 4u;
            CP_ASYNC16(dst, Abase + (size_t)(k0 + k) * HW + m4);
        }
        #pragma unroll
        for (int i = 0; i < 2; i++) {
            int lin = t + i * 256;
            int n   = lin >> 2;
            int k4  = (lin & 3) << 2;
            unsigned dst = uB + ((unsigned)(buf * 128 + n) * BSTR + k4) * 4u;
            CP_ASYNC16(dst, Wmat + (size_t)n * CIN + CDIR + k0 + k4);
        }
        CP_COMMIT();
    };

    load_stage(0, 0);

    for (int s = 0; s < 16; s++) {
        int buf = s & 1;
        if (s + 1 < 16) { load_stage(s + 1, buf ^ 1); CP_WAIT(1); }
        else            { CP_WAIT(0); }
        __syncthreads();

        #pragma unroll
        for (int kk = 0; kk < 16; kk += 8) {
            int kc = kk + ql;
            unsigned a[2][4], bb[8][2];
            #pragma unroll
            for (int mt = 0; mt < 2; mt++) {
                int r = wm * 32 + mt * 16 + qg;
                a[mt][0] = __float_as_uint(As[buf][kc][r]);
                a[mt][1] = __float_as_uint(As[buf][kc][r + 8]);
                a[mt][2] = __float_as_uint(As[buf][kc + 4][r]);
                a[mt][3] = __float_as_uint(As[buf][kc + 4][r + 8]);
            }
            #pragma unroll
            for (int nt = 0; nt < 8; nt++) {
                int c = wn * 64 + nt * 8 + qg;
                bb[nt][0] = __float_as_uint(Bs[buf][c][kc]);
                bb[nt][1] = __float_as_uint(Bs[buf][c][kc + 4]);
            }
            #pragma unroll
            for (int mt = 0; mt < 2; mt++)
                #pragma unroll
                for (int nt = 0; nt < 8; nt++)
                    mma_tf32(acc[mt][nt], a[mt], bb[nt]);
        }
        __syncthreads();
    }

    // epilogue: write G as fp16
    #pragma unroll
    for (int mt = 0; mt < 2; mt++) {
        int r0 = pixBase + wm * 32 + mt * 16 + qg;
        #pragma unroll
        for (int nt = 0; nt < 8; nt++) {
            int n = wn * 64 + nt * 8 + 2 * ql;
            *(__half2*)&g_G[(size_t)r0 * COUT + n] =
                __floats2half2_rn(acc[mt][nt][0], acc[mt][nt][1]);
            *(__half2*)&g_G[(size_t)(r0 + 8) * COUT + n] =
                __floats2half2_rn(acc[mt][nt][2], acc[mt][nt][3]);
        }
    }
}

// ---------------------------------------------------------------------------
// Kernel B: direct GEMM (K=176, tf32) + warp-coalesced bilinear gather of
//           fp16 G via smem bev tile + BN + ReLU.
// Dynamic smem union: [ As(20480) | Bs(20480) ] overlaid with bev(67584),
// then pixs/wgts/scale/shift.
// ---------------------------------------------------------------------------
#define ASTR_Q   20
#define BEVSTR   132
#define OFF_BS   20480
#define OFF_PIX  67584
#define OFF_WGT  69632
#define OFF_SCL  71680
#define OFF_SHF  72192
#define SMEM_PT  72704

__global__ __launch_bounds__(256, 2)
void point_kernel(const float* __restrict__ pc,
                  const float* __restrict__ f16,
                  const float* __restrict__ f32,
                  const float* __restrict__ f64a,
                  const float* __restrict__ f64b,
                  const float* __restrict__ Wmat,
                  const float* __restrict__ gamma,
                  const float* __restrict__ beta,
                  const float* __restrict__ mean,
                  const float* __restrict__ var,
                  float* __restrict__ out) {
    extern __shared__ char smem_raw[];
    float (*As)[128][ASTR_Q] = (float (*)[128][ASTR_Q])(smem_raw);
    float (*Bs)[128][BSTR]   = (float (*)[128][BSTR])(smem_raw + OFF_BS);
    float (*bev)[BEVSTR]     = (float (*)[BEVSTR])(smem_raw);
    int   (*pixs)[128]       = (int (*)[128])(smem_raw + OFF_PIX);
    float (*wgts)[128]       = (float (*)[128])(smem_raw + OFF_WGT);
    float* scale_s           = (float*)(smem_raw + OFF_SCL);
    float* shift_s           = (float*)(smem_raw + OFF_SHF);

    const int t    = threadIdx.x;
    const int lane = t & 31;
    const int wid  = t >> 5;
    const int wm   = wid & 3;
    const int wn   = wid >> 2;
    const int qg   = lane >> 2;
    const int ql   = lane & 3;

    const int mBase = blockIdx.x * 128;

    if (t < 128) {
        float4 p = *(const float4*)(pc + (size_t)(mBase + t) * 4);
        int   bb = (int)p.x;
        float x  = (p.y - 0.0f) / 0.05f / 8.0f;
        float y  = (p.z - (-40.0f)) / 0.05f / 8.0f;
        int xf = (int)floorf(x);
        int yf = (int)floorf(y);
        int x0 = min(max(xf,     0), WGRID - 1);
        int x1 = min(max(xf + 1, 0), WGRID - 1);
        int y0 = min(max(yf,     0), HG - 1);
        int y1 = min(max(yf + 1, 0), HG - 1);
        float xf0 = (float)x0, xf1 = (float)x1;
        float yf0 = (float)y0, yf1 = (float)y1;
        int base = bb * HW;
        pixs[0][t] = base + y0 * WGRID + x0;
        pixs[1][t] = base + y1 * WGRID + x0;
        pixs[2][t] = base + y0 * WGRID + x1;
        pixs[3][t] = base + y1 * WGRID + x1;
        wgts[0][t] = (xf1 - x) * (yf1 - y);
        wgts[1][t] = (xf1 - x) * (y - yf0);
        wgts[2][t] = (x - xf0) * (yf1 - y);
        wgts[3][t] = (x - xf0) * (y - yf0);
    } else {
        int n = t - 128;
        float s = gamma[n] * rsqrtf(var[n] + 1e-5f);
        scale_s[n] = s;
        shift_s[n] = beta[n] - mean[n] * s;
    }

    const unsigned uA = smem_u32(&As[0][0][0]);
    const unsigned uB = smem_u32(&Bs[0][0][0]);

    float acc[2][8][4];
    #pragma unroll
    for (int i = 0; i < 2; i++)
        #pragma unroll
        for (int j = 0; j < 8; j++)
            #pragma unroll
            for (int v = 0; v < 4; v++) acc[i][j][v] = 0.0f;

    auto load_stage = [&](int s, int buf) {
        int k0 = s * 16;
        const float* fb; int fs, off;
        if (k0 < 16)       { fb = f16;  fs = 16; off = k0;       }
        else if (k0 < 48)  { fb = f32;  fs = 32; off = k0 - 16;  }
        else if (k0 < 112) { fb = f64a; fs = 64; off = k0 - 48;  }
        else               { fb = f64b; fs = 64; off = k0 - 112; }
        #pragma unroll
        for (int i = 0; i < 2; i++) {
            int lin = t + i * 256;
            int m   = lin >> 2;
            int k4  = (lin & 3) << 2;
            unsigned dst = uA + ((unsigned)(buf * 128 + m) * ASTR_Q + k4) * 4u;
            CP_ASYNC16(dst, fb + (size_t)(mBase + m) * fs + off + k4);
        }
        #pragma unroll
        for (int i = 0; i < 2; i++) {
            int lin = t + i * 256;
            int n   = lin >> 2;
            int k4  = (lin & 3) << 2;
            unsigned dst = uB + ((unsigned)(buf * 128 + n) * BSTR + k4) * 4u;
            CP_ASYNC16(dst, Wmat + (size_t)n * CIN + k0 + k4);
        }
        CP_COMMIT();
    };

    load_stage(0, 0);

    for (int s = 0; s < 11; s++) {
        int buf = s & 1;
        if (s + 1 < 11) { load_stage(s + 1, buf ^ 1); CP_WAIT(1); }
        else            { CP_WAIT(0); }
        __syncthreads();

        #pragma unroll
        for (int kk = 0; kk < 16; kk += 8) {
            int kc = kk + ql;
            unsigned a[2][4], bb[8][2];
            #pragma unroll
            for (int mt = 0; mt < 2; mt++) {
                int r = wm * 32 + mt * 16 + qg;
                a[mt][0] = __float_as_uint(As[buf][r][kc]);
                a[mt][1] = __float_as_uint(As[buf][r + 8][kc]);
                a[mt][2] = __float_as_uint(As[buf][r][kc + 4]);
                a[mt][3] = __float_as_uint(As[buf][r + 8][kc + 4]);
            }
            #pragma unroll
            for (int nt = 0; nt < 8; nt++) {
                int c = wn * 64 + nt * 8 + qg;
                bb[nt][0] = __float_as_uint(Bs[buf][c][kc]);
                bb[nt][1] = __float_as_uint(Bs[buf][c][kc + 4]);
            }
            #pragma unroll
            for (int mt = 0; mt < 2; mt++)
                #pragma unroll
                for (int nt = 0; nt < 8; nt++)
                    mma_tf32(acc[mt][nt], a[mt], bb[nt]);
        }
        __syncthreads();
    }
    // (loop ends with __syncthreads: all fragment reads of As/Bs complete)

    // --- warp-coalesced gather: each warp handles 16 points ---
    // Per point: 4 G-rows (256B fp16 each), loaded coalesced (8B/lane),
    // weighted sum in fp32, stored as the bev tile row.
    {
        int p0 = wid * 16;
        #pragma unroll 4
        for (int i = 0; i < 16; i++) {
            int m = p0 + i;
            float4 sum = make_float4(0.f, 0.f, 0.f, 0.f);
            #pragma unroll
            for (int nb = 0; nb < 4; nb++) {
                float w = wgts[nb][m];
                const __half* rp = g_G + (size_t)pixs[nb][m] * COUT + lane * 4;
                uint2 u = *(const uint2*)rp;
                float2 f0 = __half22float2(*(__half2*)&u.x);
                float2 f1 = __half22float2(*(__half2*)&u.y);
                sum.x += w * f0.x; sum.y += w * f0.y;
                sum.z += w * f1.x; sum.w += w * f1.y;
            }
            *(float4*)&bev[m][lane * 4] = sum;
        }
    }
    __syncthreads();

    // add bev tile into fragments
    #pragma unroll
    for (int mt = 0; mt < 2; mt++)
        #pragma unroll
        for (int h = 0; h < 2; h++) {
            int ml = wm * 32 + mt * 16 + h * 8 + qg;
            #pragma unroll
            for (int nt = 0; nt < 8; nt++) {
                float2 g = *(const float2*)&bev[ml][wn * 64 + nt * 8 + 2 * ql];
                acc[mt][nt][2 * h + 0] += g.x;
                acc[mt][nt][2 * h + 1] += g.y;
            }
        }

    // BN + ReLU + store
    #pragma unroll
    for (int nt = 0; nt < 8; nt++) {
        int n = wn * 64 + nt * 8 + 2 * ql;
        float s0 = scale_s[n],     h0 = shift_s[n];
        float s1 = scale_s[n + 1], h1 = shift_s[n + 1];
        #pragma unroll
        for (int mt = 0; mt < 2; mt++) {
            int m = mBase + wm * 32 + mt * 16 + qg;
            *(float2*)&out[(size_t)m * COUT + n] =
                make_float2(fmaxf(acc[mt][nt][0] * s0 + h0, 0.0f),
                            fmaxf(acc[mt][nt][1] * s1 + h1, 0.0f));
            *(float2*)&out[(size_t)(m + 8) * COUT + n] =
                make_float2(fmaxf(acc[mt][nt][2] * s0 + h0, 0.0f),
                            fmaxf(acc[mt][nt][3] * s1 + h1, 0.0f));
        }
    }
}

// ---------------------------------------------------------------------------
extern "C" void kernel_launch(void* const* d_in, const int* in_sizes, int n_in,
                              void* d_out, int out_size) {
    const float* point_coords = (const float*)d_in[0];
    const float* spatial      = (const float*)d_in[1];
    const float* feat16       = (const float*)d_in[2];
    const float* feat32       = (const float*)d_in[3];
    const float* feat64a      = (const float*)d_in[4];
    const float* feat64b      = (const float*)d_in[5];
    const float* Wmat         = (const float*)d_in[6];
    const float* gamma        = (const float*)d_in[7];
    const float* beta         = (const float*)d_in[8];
    const float* rmean        = (const float*)d_in[9];
    const float* rvar         = (const float*)d_in[10];
    float* out = (float*)d_out;

    cudaFuncSetAttribute(point_kernel,
                         cudaFuncAttributeMaxDynamicSharedMemorySize, SMEM_PT);

    proj_kernel<<<NPIX / 128, 256>>>(spatial, Wmat);
    point_kernel<<<NPTS / 128, 256, SMEM_PT>>>(point_coords, feat16, feat32,
                                               feat64a, feat64b, Wmat,
                                               gamma, beta, rmean, rvar, out);
}